// round 2
// baseline (speedup 1.0000x reference)
#include <cuda_runtime.h>

#define TOKENS  65536
#define KCODES  1024
#define DDIM    64
#define HW      4096
#define TM      128
#define TN      128
#define SROW    65
#define SMEM_BYTES ((TM*SROW + TN*SROW + TN) * 4)

__device__ float g_hn[KCODES];
__device__ int   g_idx[TOKENS];

// Kernel 0: half squared norms of codebook rows
__global__ void vq_norms(const float* __restrict__ cb) {
    int j = blockIdx.x * blockDim.x + threadIdx.x;
    if (j < KCODES) {
        float s = 0.f;
        #pragma unroll
        for (int d = 0; d < DDIM; ++d) { float v = cb[j*DDIM + d]; s += v*v; }
        g_hn[j] = 0.5f * s;
    }
}

// Kernel 1: argmax over (x.c - 0.5*|c|^2) == argmin of squared L2 distance.
// 128 tokens x 128-code chunks, 16x16 threads, 8x8 per-thread tile,
// accumulators packed as f32x2 pairs (2 tokens per 64-bit register).
__global__ __launch_bounds__(256, 2)
void vq_main(const float* __restrict__ inp, const float* __restrict__ cb,
             float* __restrict__ out, int out_size) {
    extern __shared__ float smem[];
    float* sx  = smem;              // TM x SROW (token tile, [token][d])
    float* sc  = sx + TM * SROW;    // TN x SROW (code tile,  [code][d])
    float* shn = sc + TN * SROW;    // TN half-norms

    int tid = threadIdx.x;
    int tx = tid & 15, ty = tid >> 4;
    int n0 = blockIdx.x * TM;              // 128 consecutive tokens, same batch b
    int b  = n0 / HW, s0 = n0 % HW;
    const float* ibase = inp + (long long)b * DDIM * HW + s0;

    // Load x-tile: input is (B, D, H, W) -> x[token][d] = ibase[d*HW + t]
    for (int e = tid; e < TM * DDIM; e += 256) {
        int d = e >> 7, t = e & 127;
        sx[t * SROW + d] = ibase[d * HW + t];
    }

    unsigned long long acc[4][8];
    #pragma unroll
    for (int p = 0; p < 4; ++p)
        #pragma unroll
        for (int j = 0; j < 8; ++j) acc[p][j] = 0ull;

    float bestv[8]; int besti[8];
    #pragma unroll
    for (int i = 0; i < 8; ++i) { bestv[i] = -3.4e38f; besti[i] = 0; }

    for (int c0 = 0; c0 < KCODES; c0 += TN) {
        __syncthreads();
        // Load code chunk (rows contiguous in gmem)
        for (int e = tid; e < TN * DDIM; e += 256) {
            int c = e >> 6, k = e & 63;
            sc[c * SROW + k] = cb[(c0 + c) * DDIM + k];
        }
        if (tid < TN) shn[tid] = g_hn[c0 + tid];
        __syncthreads();

        #pragma unroll 4
        for (int k = 0; k < DDIM; ++k) {
            float a[8]; unsigned long long ax[4];
            #pragma unroll
            for (int i = 0; i < 8; ++i) a[i] = sx[(ty + 16*i) * SROW + k];
            #pragma unroll
            for (int p = 0; p < 4; ++p)
                asm("mov.b64 %0, {%1, %2};" : "=l"(ax[p]) : "f"(a[2*p]), "f"(a[2*p+1]));
            #pragma unroll
            for (int j = 0; j < 8; ++j) {
                float bval = sc[(tx + 16*j) * SROW + k];
                unsigned long long bx;
                asm("mov.b64 %0, {%1, %1};" : "=l"(bx) : "f"(bval));
                #pragma unroll
                for (int p = 0; p < 4; ++p)
                    asm("fma.rn.f32x2 %0, %1, %2, %0;"
                        : "+l"(acc[p][j]) : "l"(ax[p]), "l"(bx));
            }
        }

        // Chunk epilogue: score = dot - 0.5*|c|^2, track running best per token
        #pragma unroll
        for (int j = 0; j < 8; ++j) {
            float hn = shn[tx + 16*j];
            int c = c0 + tx + 16*j;
            #pragma unroll
            for (int p = 0; p < 4; ++p) {
                float lo, hi;
                asm("mov.b64 {%0, %1}, %2;" : "=f"(lo), "=f"(hi) : "l"(acc[p][j]));
                acc[p][j] = 0ull;
                float v0 = lo - hn, v1 = hi - hn;
                if (v0 > bestv[2*p])     { bestv[2*p]   = v0; besti[2*p]   = c; }
                if (v1 > bestv[2*p + 1]) { bestv[2*p+1] = v1; besti[2*p+1] = c; }
            }
        }
    }

    // Reduce across the 16 code-lanes (tx) sharing each token row.
    // lane = (ty&1)*16 + tx, so xor masks 1..8 stay within the tx group.
    #pragma unroll
    for (int i = 0; i < 8; ++i) {
        float v = bestv[i]; int ix = besti[i];
        #pragma unroll
        for (int m = 8; m >= 1; m >>= 1) {
            float ov = __shfl_xor_sync(0xffffffffu, v,  m);
            int   oi = __shfl_xor_sync(0xffffffffu, ix, m);
            if (ov > v || (ov == v && oi < ix)) { v = ov; ix = oi; }
        }
        if (tx == 0) {
            int n = n0 + ty + 16*i;
            g_idx[n] = ix;
            if (out_size > TOKENS * DDIM)            // indices output (as float)
                out[TOKENS * DDIM + n] = (float)ix;
        }
    }
}

// Kernel 2: gather codebook rows into (B, D, H, W) layout, fully coalesced.
__global__ void vq_gather(const float* __restrict__ cb, float* __restrict__ out) {
    int e = blockIdx.x * 256 + threadIdx.x;       // e = b*2^18 + d*2^12 + s
    int bb = e >> 18;
    int d  = (e >> 12) & 63;
    int s  = e & 4095;
    int n  = (bb << 12) + s;
    out[e] = cb[g_idx[n] * DDIM + d];
}

extern "C" void kernel_launch(void* const* d_in, const int* in_sizes, int n_in,
                              void* d_out, int out_size) {
    const float* inp = (const float*)d_in[0];   // (16, 64, 64, 64) f32
    const float* cb  = (const float*)d_in[1];   // (1024, 64) f32
    float* out = (float*)d_out;

    cudaFuncSetAttribute(vq_main, cudaFuncAttributeMaxDynamicSharedMemorySize,
                         SMEM_BYTES);

    vq_norms<<<(KCODES + 255) / 256, 256>>>(cb);
    vq_main<<<TOKENS / TM, 256, SMEM_BYTES>>>(inp, cb, out, out_size);
    vq_gather<<<(TOKENS * DDIM) / 256, 256>>>(cb, out);
}

// round 3
// speedup vs baseline: 1.4853x; 1.4853x over previous
#include <cuda_runtime.h>

#define TOKENS  65536
#define KCODES  1024
#define DDIM    64
#define HW      4096
#define TM      128
#define TN      64
#define SROW    66          // padded row stride (floats); keeps LDS.64 aligned, conflict-free
#define NCHUNK  (KCODES / TN)

typedef unsigned long long ull;

__device__ float g_hn[KCODES];

// Kernel 0: half squared norms, one warp per codebook row (coalesced + shfl reduce)
__global__ void vq_norms(const float* __restrict__ cb) {
    int w    = (blockIdx.x * blockDim.x + threadIdx.x) >> 5;
    int lane = threadIdx.x & 31;
    if (w < KCODES) {
        float v0 = cb[w * DDIM + lane];
        float v1 = cb[w * DDIM + 32 + lane];
        float s = v0 * v0 + v1 * v1;
        #pragma unroll
        for (int m = 16; m >= 1; m >>= 1) s += __shfl_xor_sync(0xffffffffu, s, m);
        if (lane == 0) g_hn[w] = 0.5f * s;
    }
}

// Kernel 1: argmax(x.c - 0.5*|c|^2) with K-dim f32x2 packing (no pack movs),
// fused codebook gather + index write in the epilogue.
// 128 tokens x 64-code chunks, 16x16 threads, 8 tokens x 4 codes per thread.
__global__ __launch_bounds__(256, 2)
void vq_main(const float* __restrict__ inp, const float* __restrict__ cb,
             float* __restrict__ out, int out_size) {
    extern __shared__ float smem[];
    float* sx   = smem;                  // [128][SROW]  token tile, [t][d]
    float* sc   = sx + TM * SROW;        // [64][SROW]   code tile,  [c][d]
    float* shn  = sc + TN * SROW;        // [64]         half norms
    int*   sidx = (int*)(shn + TN);      // [128]        winning index per token

    int tid = threadIdx.x;
    int tx = tid & 15, ty = tid >> 4;
    int n0 = blockIdx.x * TM;            // 128 consecutive tokens, same batch b
    int b  = n0 >> 12, s0 = n0 & (HW - 1);
    const float* ibase = inp + (long long)b * DDIM * HW + s0;

    // Load x-tile: x[t][d] = ibase[d*HW + t] (gmem reads coalesced over t)
    for (int e = tid; e < TM * DDIM; e += 256) {
        int d = e >> 7, t = e & 127;
        sx[t * SROW + d] = ibase[d * HW + t];
    }

    float bestv[8]; int besti[8];
    #pragma unroll
    for (int i = 0; i < 8; ++i) { bestv[i] = -3.4e38f; besti[i] = 0; }

    const float* axb = sx + ty * SROW;   // a base: token t = ty + 16p
    const float* bxb = sc + tx * SROW;   // b base: code  c = tx + 16q

    for (int c0 = 0; c0 < KCODES; c0 += TN) {
        __syncthreads();
        // Load code chunk (gmem rows contiguous, smem stores conflict-free)
        for (int e = tid; e < TN * DDIM; e += 256) {
            int c = e >> 6, k = e & 63;
            sc[c * SROW + k] = cb[(c0 + c) * DDIM + k];
        }
        if (tid < TN) shn[tid] = g_hn[c0 + tid];
        __syncthreads();

        ull acc[8][4];
        #pragma unroll
        for (int p = 0; p < 8; ++p)
            #pragma unroll
            for (int q = 0; q < 4; ++q) acc[p][q] = 0ull;

        // K-pair mainloop: acc.lo accumulates even k, acc.hi odd k.
        #pragma unroll 4
        for (int k2 = 0; k2 < DDIM / 2; ++k2) {
            ull a[8], bb[4];
            #pragma unroll
            for (int p = 0; p < 8; ++p)            // broadcast loads (2 addrs/warp)
                a[p] = *(const ull*)(axb + p * 16 * SROW + 2 * k2);
            #pragma unroll
            for (int q = 0; q < 4; ++q)            // 16 addrs/warp, all banks once
                bb[q] = *(const ull*)(bxb + q * 16 * SROW + 2 * k2);
            #pragma unroll
            for (int p = 0; p < 8; ++p)
                #pragma unroll
                for (int q = 0; q < 4; ++q)
                    asm("fma.rn.f32x2 %0, %1, %2, %0;"
                        : "+l"(acc[p][q]) : "l"(a[p]), "l"(bb[q]));
        }

        // Chunk epilogue: score = (even+odd) - 0.5|c|^2, running argmax.
        // Strict > keeps the lowest index on ties (chunks ascend, q ascends).
        #pragma unroll
        for (int q = 0; q < 4; ++q) {
            float hn = shn[tx + 16 * q];
            int cg = c0 + tx + 16 * q;
            #pragma unroll
            for (int p = 0; p < 8; ++p) {
                float lo, hi;
                asm("mov.b64 {%0, %1}, %2;" : "=f"(lo), "=f"(hi) : "l"(acc[p][q]));
                float v = (lo + hi) - hn;
                if (v > bestv[p]) { bestv[p] = v; besti[p] = cg; }
            }
        }
    }

    // Reduce across the 16 code-lanes (tx). lane = (ty&1)*16 + tx, so xor
    // masks 8..1 stay within the tx group.
    #pragma unroll
    for (int p = 0; p < 8; ++p) {
        float v = bestv[p]; int ix = besti[p];
        #pragma unroll
        for (int m = 8; m >= 1; m >>= 1) {
            float ov = __shfl_xor_sync(0xffffffffu, v,  m);
            int   oi = __shfl_xor_sync(0xffffffffu, ix, m);
            if (ov > v || (ov == v && oi < ix)) { v = ov; ix = oi; }
        }
        if (tx == 0) sidx[ty + 16 * p] = ix;
    }
    __syncthreads();

    // Fused gather: out[b][d][s0+t] = cb[idx[t]][d]; writes coalesced over t,
    // reads hit L2-resident codebook.
    for (int e = tid; e < TM * DDIM; e += 256) {
        int d = e >> 7, t = e & 127;
        out[((long long)b * DDIM + d) * HW + s0 + t] = cb[sidx[t] * DDIM + d];
    }
    // Index plane (as float, exact for idx < 2^24)
    if (out_size > TOKENS * DDIM && tid < TM)
        out[TOKENS * DDIM + n0 + tid] = (float)sidx[tid];
}

#define SMEM_BYTES (((TM + TN) * SROW + TN) * 4 + TM * 4)

extern "C" void kernel_launch(void* const* d_in, const int* in_sizes, int n_in,
                              void* d_out, int out_size) {
    const float* inp = (const float*)d_in[0];   // (16, 64, 64, 64) f32
    const float* cb  = (const float*)d_in[1];   // (1024, 64) f32
    float* out = (float*)d_out;

    cudaFuncSetAttribute(vq_main, cudaFuncAttributeMaxDynamicSharedMemorySize,
                         SMEM_BYTES);

    vq_norms<<<KCODES * 32 / 256, 256>>>(cb);
    vq_main<<<TOKENS / TM, 256, SMEM_BYTES>>>(inp, cb, out, out_size);
}